// round 13
// baseline (speedup 1.0000x reference)
#include <cuda_runtime.h>
#include <cuda_bf16.h>
#include <cstdint>

#define B_    32
#define T_    512
#define H_    256
#define WDIM_ 300
#define KP_   304   // padded WDIM

typedef unsigned long long u64;

// ---------------- scratch (device globals; no allocation allowed) ----------------
__device__ __align__(16) __nv_bfloat16 g_ehi[16384 * KP_];       // emb gather hi [r][k]
__device__ __align__(16) __nv_bfloat16 g_elo[16384 * KP_];       // emb gather lo [r][k]
__device__ __align__(16) __nv_bfloat16 g_w1[2][256][KP_];        // Win split [part][c][k]
__device__ __align__(16) __nv_bfloat16 g_zhi[16384 * 256];       // z split hi  [r][k]
__device__ __align__(16) __nv_bfloat16 g_zlo[16384 * 256];       // z split lo  [r][k]
__device__ __align__(16) __nv_bfloat16 g_wt[2][2][1024][256];    // [dir][part][c][k]
__device__ __align__(16) float g_gates[2 * 512 * 1024 * 32];     // [dir][t][col][b] 128 MB
__device__ __align__(16) float g_h[2][2][256 * 32];              // [buf][dir][k][b]
__device__ __align__(16) float g_hsum[512 * 32];                 // [feat][b]
__device__ __align__(16) float g_fc[256 * 32];                   // [j][b]
__device__ unsigned g_arrive[2];
__device__ unsigned g_gen[2];
__device__ __align__(128) unsigned g_flags[2][64];               // monotonic publish counters

__device__ __forceinline__ float sigf(float x) { return 1.0f / (1.0f + __expf(-x)); }

__device__ __forceinline__ unsigned ldacq(const unsigned* p) {
    unsigned v;
    asm volatile("ld.acquire.gpu.global.u32 %0, [%1];" : "=r"(v) : "l"(p) : "memory");
    return v;
}
__device__ __forceinline__ void red_release_add1(unsigned* p) {
    asm volatile("red.release.gpu.global.add.u32 [%0], 1;" :: "l"(p) : "memory");
}

// warp-level bf16 MMA (sm_80+ baseline; works on compute_103)
__device__ __forceinline__ void mma16816(float* c, const unsigned* a, unsigned b0, unsigned b1) {
    asm volatile(
        "mma.sync.aligned.m16n8k16.row.col.f32.bf16.bf16.f32 "
        "{%0,%1,%2,%3}, {%4,%5,%6,%7}, {%8,%9}, {%0,%1,%2,%3};"
        : "+f"(c[0]), "+f"(c[1]), "+f"(c[2]), "+f"(c[3])
        : "r"(a[0]), "r"(a[1]), "r"(a[2]), "r"(a[3]), "r"(b0), "r"(b1));
}

// cp.async 16B (sm_80+ baseline)
__device__ __forceinline__ void cpa16(const void* sptr, const void* gptr) {
    unsigned sa = (unsigned)__cvta_generic_to_shared(sptr);
    asm volatile("cp.async.cg.shared.global [%0], [%1], 16;" :: "r"(sa), "l"(gptr));
}

__device__ __forceinline__ void bf16split(float v, __nv_bfloat16& h, __nv_bfloat16& l) {
    h = __float2bfloat16(v);
    l = __float2bfloat16(v - __bfloat162float(h));
}

// Sense-reversing barrier among the 64 CTAs of one direction (used ONCE at start of k3).
__device__ __forceinline__ void dir_barrier(int dir, unsigned ncta) {
    __syncthreads();
    if (threadIdx.x == 0) {
        volatile unsigned* gen = &g_gen[dir];
        unsigned old = *gen;
        __threadfence();
        unsigned a = atomicAdd(&g_arrive[dir], 1u);
        if (a == ncta - 1u) {
            g_arrive[dir] = 0u;
            __threadfence();
            atomicExch((unsigned*)&g_gen[dir], old + 1u);
        } else {
            while (*gen == old) { }
        }
        __threadfence();
    }
    __syncthreads();
}

// ---------------- kernel 1a: gather + split emb[x] rows -> g_ehi/g_elo ----------------
// warp per row: r = blockIdx.x*8 + warp; r = t*32 + b
__global__ void k1a_gather(const float* __restrict__ emb, const int* __restrict__ x) {
    int tid = threadIdx.x;
    int warp = tid >> 5, lane = tid & 31;
    int r = blockIdx.x * 8 + warp;
    int t = r >> 5, b = r & 31;
    const float* src = emb + (size_t)x[b * T_ + t] * WDIM_;
    for (int k = lane; k < KP_; k += 32) {
        float v = (k < WDIM_) ? __ldg(&src[k]) : 0.0f;
        __nv_bfloat16 h, l;
        bf16split(v, h, l);
        g_ehi[(size_t)r * KP_ + k] = h;
        g_elo[(size_t)r * KP_ + k] = l;
    }
}

// ---------------- kernel 1w: split Win -> g_w1[part][c][k] (zero-padded) ----------------
__global__ void k1w_conv(const float* __restrict__ Win) {
    int c = blockIdx.x;         // 256
    int k = threadIdx.x;        // 304
    float w = (k < WDIM_) ? Win[(size_t)k * H_ + c] : 0.0f;
    __nv_bfloat16 h, l;
    bf16split(w, h, l);
    g_w1[0][c][k] = h;
    g_w1[1][c][k] = l;
}

// ---------------- kernel 1b: pipelined HMMA: z = relu(E @ Win + bin) -> splits ----------
// CTA tile 128x64, K-chunk 16, two cp.async stages. 57 chunks = 3 terms x 19.
#define EST 24   // smem row stride (bf16): 12 words -> conflict-free frags
__global__ void __launch_bounds__(256) k1b_hmma(const float* __restrict__ bin) {
    __shared__ __align__(16) __nv_bfloat16 sm[2][(128 + 64) * EST];   // 18432 B
    float* Sc = (float*)sm;                                           // epilogue alias

    int tid = threadIdx.x;
    int wid = tid >> 5, lane = tid & 31;
    int g = lane >> 2, tg = lane & 3;
    int wm = wid & 3, wn = wid >> 2;
    int bx = blockIdx.x, by = blockIdx.y;
    int r0 = bx * 128;
    int c0 = by * 64;
    int m0 = wm * 32;
    int n0 = wn * 32;
    int arow = tid >> 1, ahalf = tid & 1;     // A loader: 128 rows x 2
    int brow = (tid & 127) >> 1, bhalf = tid & 1;  // B loader: tid<128

    float c[2][4][4];
#pragma unroll
    for (int mi = 0; mi < 2; ++mi)
#pragma unroll
        for (int ni = 0; ni < 4; ++ni)
#pragma unroll
            for (int q = 0; q < 4; ++q) c[mi][ni][q] = 0.0f;

    auto prefetch = [&](int it) {
        int seg = (it >= 38) ? 2 : ((it >= 19) ? 1 : 0);
        int chunk = it - seg * 19;
        const __nv_bfloat16* Ag = (seg < 2) ? g_ehi : g_elo;
        const __nv_bfloat16* Bg = &g_w1[(seg == 1) ? 1 : 0][c0][0];
        int st = it & 1;
        __nv_bfloat16* base = sm[st];
        // A: 128 rows x 16 k
        cpa16(base + arow * EST + ahalf * 8,
              Ag + (size_t)(r0 + arow) * KP_ + chunk * 16 + ahalf * 8);
        // B: 64 cols x 16 k
        if (tid < 128)
            cpa16(base + (128 + brow) * EST + bhalf * 8,
                  Bg + (size_t)brow * KP_ + chunk * 16 + bhalf * 8);
        asm volatile("cp.async.commit_group;" ::: "memory");
    };

    prefetch(0);
    for (int it = 0; it < 57; ++it) {
        asm volatile("cp.async.wait_group 0;" ::: "memory");
        __syncthreads();
        if (it < 56) prefetch(it + 1);
        const __nv_bfloat16* As = sm[it & 1];
        const __nv_bfloat16* Bs = As + 128 * EST;
        unsigned a[2][4];
#pragma unroll
        for (int mi = 0; mi < 2; ++mi) {
            const __nv_bfloat16* ab = As + (m0 + mi * 16 + g) * EST + tg * 2;
            a[mi][0] = *(const unsigned*)ab;
            a[mi][1] = *(const unsigned*)(ab + 8 * EST);
            a[mi][2] = *(const unsigned*)(ab + 8);
            a[mi][3] = *(const unsigned*)(ab + 8 * EST + 8);
        }
#pragma unroll
        for (int ni = 0; ni < 4; ++ni) {
            const __nv_bfloat16* bb = Bs + (n0 + ni * 8 + g) * EST + tg * 2;
            unsigned b0 = *(const unsigned*)bb;
            unsigned b1 = *(const unsigned*)(bb + 8);
            mma16816(c[0][ni], a[0], b0, b1);
            mma16816(c[1][ni], a[1], b0, b1);
        }
    }
    __syncthreads();   // MMAs done before Sc (alias) writes

    // epilogue: slab transpose -> bias + relu + split -> packed 16B stores [r][k]
    float* myS = Sc + wid * (8 * 33);
#pragma unroll
    for (int ni = 0; ni < 4; ++ni) {
#pragma unroll
        for (int mi = 0; mi < 2; ++mi)
#pragma unroll
            for (int q = 0; q < 4; ++q) {
                int col_local = tg * 2 + (q & 1);
                int row_local = mi * 16 + g + ((q >> 1) ? 8 : 0);
                myS[col_local * 33 + row_local] = c[mi][ni][q];
            }
        __syncwarp();
        // lane = row (0..31): 8 cols -> one uint4 per array
        // NOTE: only rows m0..m0+31 of this warp: but slab holds 32 rows (mi*16+g+8q covers 0..31)
        int rg = r0 + m0 + lane;
        int kg = c0 + n0 + ni * 8;
        unsigned hiw[4], low[4];
#pragma unroll
        for (int cp = 0; cp < 4; ++cp) {
            float v0 = fmaxf(myS[(2 * cp + 0) * 33 + lane] + __ldg(&bin[kg + 2 * cp + 0]), 0.0f);
            float v1 = fmaxf(myS[(2 * cp + 1) * 33 + lane] + __ldg(&bin[kg + 2 * cp + 1]), 0.0f);
            __nv_bfloat16 h0, l0, h1, l1;
            bf16split(v0, h0, l0);
            bf16split(v1, h1, l1);
            __nv_bfloat162 ph{h0, h1}, pl{l0, l1};
            hiw[cp] = *(unsigned*)&ph;
            low[cp] = *(unsigned*)&pl;
        }
        *(uint4*)&g_zhi[(size_t)rg * 256 + kg] = make_uint4(hiw[0], hiw[1], hiw[2], hiw[3]);
        *(uint4*)&g_zlo[(size_t)rg * 256 + kg] = make_uint4(low[0], low[1], low[2], low[3]);
        __syncwarp();
    }
}

// ---------------- kernel 2w: split/transpose Wih -> g_wt[dir][part][c][k] ----------------
__global__ void k2w_conv(const float* __restrict__ Wf, const float* __restrict__ Wb) {
    int gid = blockIdx.x * 256 + threadIdx.x;     // 2*1024*256 total
    int k = gid & 255;
    int c = (gid >> 8) & 1023;
    int dir = gid >> 18;
    float w = (dir ? Wb : Wf)[(size_t)k * 1024 + c];
    __nv_bfloat16 hi, lo;
    bf16split(w, hi, lo);
    g_wt[dir][0][c][k] = hi;
    g_wt[dir][1][c][k] = lo;
}

// ---------------- kernel 2: pipelined HMMA bf16-split GEMM: gates = z @ Wih + bl ----------
#define BST 40   // smem row stride in bf16 elements
__global__ void __launch_bounds__(256) k2_hmma(const float* __restrict__ blf,
                                               const float* __restrict__ blb) {
    __shared__ __align__(16) __nv_bfloat16 sm[2][2][128 * BST];  // 40960 B
    float* Sc = (float*)sm;                                      // epilogue alias

    int tid = threadIdx.x;
    int wid = tid >> 5, lane = tid & 31;
    int g = lane >> 2, tg = lane & 3;
    int wm = wid & 3, wn = wid >> 2;
    int bx = blockIdx.x, by = blockIdx.y;
    int dir = by >> 3;
    int c0  = (by & 7) * 128;
    int r0  = bx * 128;
    int row2 = tid >> 1, half = tid & 1;

    float c[2][8][4];
#pragma unroll
    for (int mi = 0; mi < 2; ++mi)
#pragma unroll
        for (int ni = 0; ni < 8; ++ni)
#pragma unroll
            for (int q = 0; q < 4; ++q) c[mi][ni][q] = 0.0f;

    int m0 = wm * 32;
    int n0 = wn * 64;

    auto prefetch = [&](int it) {
        int seg = it >> 3, chunk = it & 7;
        const __nv_bfloat16* Ag = (seg < 2) ? g_zhi : g_zlo;
        const __nv_bfloat16* Bg = &g_wt[dir][(seg == 1) ? 1 : 0][c0][0];
        int st = it & 1;
        const __nv_bfloat16* as = Ag + (size_t)(r0 + row2) * 256 + chunk * 32 + half * 16;
        const __nv_bfloat16* bs = Bg + (size_t)row2 * 256 + chunk * 32 + half * 16;
        __nv_bfloat16* ad = &sm[st][0][row2 * BST + half * 16];
        __nv_bfloat16* bd = &sm[st][1][row2 * BST + half * 16];
        cpa16(ad, as); cpa16(ad + 8, as + 8);
        cpa16(bd, bs); cpa16(bd + 8, bs + 8);
        asm volatile("cp.async.commit_group;" ::: "memory");
    };

    prefetch(0);
    for (int it = 0; it < 24; ++it) {
        asm volatile("cp.async.wait_group 0;" ::: "memory");
        __syncthreads();
        if (it < 23) prefetch(it + 1);
        int st = it & 1;
        const __nv_bfloat16* As = sm[st][0];
        const __nv_bfloat16* Bs = sm[st][1];
#pragma unroll
        for (int ks = 0; ks < 2; ++ks) {
            int k1 = ks * 16;
            unsigned a[2][4];
#pragma unroll
            for (int mi = 0; mi < 2; ++mi) {
                const __nv_bfloat16* ab = As + (m0 + mi * 16 + g) * BST + k1 + tg * 2;
                a[mi][0] = *(const unsigned*)ab;
                a[mi][1] = *(const unsigned*)(ab + 8 * BST);
                a[mi][2] = *(const unsigned*)(ab + 8);
                a[mi][3] = *(const unsigned*)(ab + 8 * BST + 8);
            }
#pragma unroll
            for (int ni = 0; ni < 8; ++ni) {
                const __nv_bfloat16* bb = Bs + (n0 + ni * 8 + g) * BST + k1 + tg * 2;
                unsigned b0 = *(const unsigned*)bb;
                unsigned b1 = *(const unsigned*)(bb + 8);
                mma16816(c[0][ni], a[0], b0, b1);
                mma16816(c[1][ni], a[1], b0, b1);
            }
        }
    }
    __syncthreads();   // all MMAs done before Sc (alias) writes

    const float* bl = dir ? blb : blf;
    int t = bx * 4 + wm;
    float* myS = Sc + wid * (8 * 33);
    size_t gbase = (size_t)(dir * 512 + t) * (1024 * 32);
#pragma unroll
    for (int ni = 0; ni < 8; ++ni) {
#pragma unroll
        for (int mi = 0; mi < 2; ++mi)
#pragma unroll
            for (int q = 0; q < 4; ++q) {
                int col_local = tg * 2 + (q & 1);
                int row_local = mi * 16 + g + ((q >> 1) ? 8 : 0);
                myS[col_local * 33 + row_local] = c[mi][ni][q];
            }
        __syncwarp();
#pragma unroll
        for (int col = 0; col < 8; ++col) {
            int cg = c0 + n0 + ni * 8 + col;
            float v = myS[col * 33 + lane] + __ldg(&bl[cg]);
            g_gates[gbase + (size_t)cg * 32 + lane] = v;
        }
        __syncwarp();
    }
}

// ---------------- kernel 3: persistent BiLSTM recurrence (R9 verbatim) ----------------
#define AST   522
#define AST_W 261
__global__ void __launch_bounds__(256, 1)
k3_lstm(const float* __restrict__ Whhf, const float* __restrict__ Whhb,
        const int* __restrict__ mask) {
    __shared__ __align__(16) __nv_bfloat16 As[32 * AST];   // 33408 B
    float* red = (float*)As;
    unsigned* Asw = (unsigned*)As;

    int cta   = blockIdx.x;
    int dir   = cta >> 6;
    int slice = cta & 63;
    int u0    = slice << 2;
    const float* Whh = dir ? Whhb : Whhf;
    int tid  = threadIdx.x;
    int warp = tid >> 5, lane = tid & 31;
    int g = lane >> 2, tg = lane & 3;
    int kbase = warp << 5;

    unsigned bhi[2][2][2], blo[2][2][2];
#pragma unroll
    for (int kt = 0; kt < 2; ++kt)
#pragma unroll
        for (int nt = 0; nt < 2; ++nt)
#pragma unroll
            for (int r = 0; r < 2; ++r) {
                int n  = nt * 8 + g;
                int gc = (n >> 2) * 256 + u0 + (n & 3);
                int k  = kbase + kt * 16 + tg * 2 + r * 8;
                float w0 = Whh[(size_t)k * 1024 + gc];
                float w1 = Whh[(size_t)(k + 1) * 1024 + gc];
                __nv_bfloat16 h0, l0, h1, l1;
                bf16split(w0, h0, l0);
                bf16split(w1, h1, l1);
                __nv_bfloat162 ph{h0, h1}, pl{l0, l1};
                bhi[kt][nt][r] = *(unsigned*)&ph;
                blo[kt][nt][r] = *(unsigned*)&pl;
            }

    int u = tid >> 5;
    int b = tid & 31;
    float c_reg = 0.0f, h_reg = 0.0f, hsum_reg = 0.0f;
    if (tid < 128) g_h[0][dir][(u0 + u) * 32 + b] = 0.0f;

    unsigned base = 0;
    const unsigned* myflag = 0;
    if (tid >= 192) {
        myflag = &g_flags[dir][tid - 192];
        base = ldacq(myflag);
    }
    dir_barrier(dir, 64);

    unsigned* pubflag = &g_flags[dir][slice];
    int kp  = lane >> 3;
    int b0c = (lane & 7) * 4;

    for (int t = 0; t < T_; ++t) {
        int cur = t & 1, nxt = cur ^ 1;
        int tt = dir ? (T_ - 1 - t) : t;

        float gpre0 = 0.f, gpre1 = 0.f, gpre2 = 0.f, gpre3 = 0.f, mval = 0.f;
        if (tid < 128) {
            const float* gp = g_gates + (size_t)(dir * 512 + tt) * (1024 * 32);
            gpre0 = gp[(0 * 256 + u0 + u) * 32 + b];
            gpre1 = gp[(1 * 256 + u0 + u) * 32 + b];
            gpre2 = gp[(2 * 256 + u0 + u) * 32 + b];
            gpre3 = gp[(3 * 256 + u0 + u) * 32 + b];
            mval  = (float)mask[b * T_ + tt];
        }

        if (tid >= 192) {
            unsigned need = 128u * (unsigned)t;
            while (ldacq(myflag) - base < need) { }
        }
        __syncthreads();

#pragma unroll
        for (int p = 0; p < 4; ++p) {
            int k = kbase + p * 8 + kp * 2;
            float4 ha = __ldcg((const float4*)&g_h[cur][dir][k * 32 + b0c]);
            float4 hb = __ldcg((const float4*)&g_h[cur][dir][(k + 1) * 32 + b0c]);
            float va[4] = {ha.x, ha.y, ha.z, ha.w};
            float vb[4] = {hb.x, hb.y, hb.z, hb.w};
#pragma unroll
            for (int j = 0; j < 4; ++j) {
                unsigned ba = __float_as_uint(va[j]);
                unsigned bb = __float_as_uint(vb[j]);
                unsigned hiw = __byte_perm(ba, bb, 0x7632);
                float ra = va[j] - __uint_as_float(ba & 0xFFFF0000u);
                float rb = vb[j] - __uint_as_float(bb & 0xFFFF0000u);
                unsigned low;
                asm("cvt.rn.bf16x2.f32 %0, %1, %2;" : "=r"(low) : "f"(rb), "f"(ra));
                int row = b0c + j;
                Asw[row * AST_W + (k >> 1)]       = hiw;
                Asw[row * AST_W + 128 + (k >> 1)] = low;
            }
        }
        __syncthreads();

        float c[2][2][4];
#pragma unroll
        for (int mi = 0; mi < 2; ++mi)
#pragma unroll
            for (int ni = 0; ni < 2; ++ni)
#pragma unroll
                for (int q = 0; q < 4; ++q) c[mi][ni][q] = 0.0f;

        unsigned afr[2][2][4];
#pragma unroll
        for (int kt = 0; kt < 2; ++kt)
#pragma unroll
            for (int mi = 0; mi < 2; ++mi) {
                const __nv_bfloat16* ab = As + (mi * 16 + g) * AST + kbase + kt * 16 + tg * 2;
                afr[kt][mi][0] = *(const unsigned*)ab;
                afr[kt][mi][1] = *(const unsigned*)(ab + 8 * AST);
                afr[kt][mi][2] = *(const unsigned*)(ab + 8);
                afr[kt][mi][3] = *(const unsigned*)(ab + 8 * AST + 8);
            }
#pragma unroll
        for (int kt = 0; kt < 2; ++kt)
#pragma unroll
            for (int mi = 0; mi < 2; ++mi)
#pragma unroll
                for (int ni = 0; ni < 2; ++ni) {
                    mma16816(c[mi][ni], afr[kt][mi], bhi[kt][ni][0], bhi[kt][ni][1]);
                    mma16816(c[mi][ni], afr[kt][mi], blo[kt][ni][0], blo[kt][ni][1]);
                }
#pragma unroll
        for (int kt = 0; kt < 2; ++kt)
#pragma unroll
            for (int mi = 0; mi < 2; ++mi) {
                const __nv_bfloat16* ab = As + (mi * 16 + g) * AST + 256 + kbase + kt * 16 + tg * 2;
                afr[kt][mi][0] = *(const unsigned*)ab;
                afr[kt][mi][1] = *(const unsigned*)(ab + 8 * AST);
                afr[kt][mi][2] = *(const unsigned*)(ab + 8);
                afr[kt][mi][3] = *(const unsigned*)(ab + 8 * AST + 8);
            }
#pragma unroll
        for (int kt = 0; kt < 2; ++kt)
#pragma unroll
            for (int mi = 0; mi < 2; ++mi)
#pragma unroll
                for (int ni = 0; ni < 2; ++ni)
                    mma16816(c[mi][ni], afr[kt][mi], bhi[kt][ni][0], bhi[kt][ni][1]);

        __syncthreads();
#pragma unroll
        for (int mi = 0; mi < 2; ++mi)
#pragma unroll
            for (int ni = 0; ni < 2; ++ni)
#pragma unroll
                for (int q = 0; q < 4; ++q) {
                    int row = mi * 16 + g + ((q >> 1) ? 8 : 0);
                    int col = ni * 8 + tg * 2 + (q & 1);
                    red[warp * 528 + col * 33 + row] = c[mi][ni][q];
                }
        __syncthreads();

        if (tid < 128) {
            float z0 = gpre0, z1 = gpre1, z2 = gpre2, z3 = gpre3;
#pragma unroll
            for (int w = 0; w < 8; ++w) {
                const float* rp = red + w * 528 + b;
                z0 += rp[(0 + u) * 33];
                z1 += rp[(4 + u) * 33];
                z2 += rp[(8 + u) * 33];
                z3 += rp[(12 + u) * 33];
            }
            float ig = sigf(z0), fg = sigf(z1);
            float gg = tanhf(z2), og = sigf(z3);
            float cn = fg * c_reg + ig * gg;
            float hn = og * tanhf(cn);
            c_reg = mval * cn + (1.0f - mval) * c_reg;
            h_reg = mval * hn + (1.0f - mval) * h_reg;
            hsum_reg += mval * h_reg;
            g_h[nxt][dir][(u0 + u) * 32 + b] = h_reg;
            red_release_add1(pubflag);
        }
    }
    if (tid < 128) g_hsum[((dir << 8) + u0 + u) * 32 + b] = hsum_reg;
}

// ---------------- kernel 4a: fc_hidden[j][b], one CTA per j ----------------
__global__ void k4a_fc(const float* __restrict__ Wfc, const float* __restrict__ bfc,
                       const int* __restrict__ lengths) {
    __shared__ float redsm[8][32];
    int j = blockIdx.x;
    int tid = threadIdx.x;
    int w = tid >> 5, lane = tid & 31;
    float acc = 0.0f;
    int f0 = w * 64;
#pragma unroll 8
    for (int f = f0; f < f0 + 64; ++f)
        acc += g_hsum[f * 32 + lane] * Wfc[(size_t)f * 256 + j];
    redsm[w][lane] = acc;
    __syncthreads();
    if (w == 0) {
        float s = 0.0f;
#pragma unroll
        for (int q = 0; q < 8; ++q) s += redsm[q][lane];
        float invlen = 1.0f / (float)lengths[lane];
        g_fc[j * 32 + lane] = fmaxf(s * invlen + bfc[j], 0.0f);
    }
}

// ---------------- kernel 4b: logits ----------------
__global__ void k4b_out(const float* __restrict__ Wout, const float* __restrict__ bout,
                        float* __restrict__ out) {
    int t = threadIdx.x;
    int b = t >> 1, lab = t & 1;
    float s = bout[lab];
#pragma unroll 8
    for (int j = 0; j < 256; ++j)
        s += g_fc[j * 32 + b] * Wout[j * 2 + lab];
    out[b * 2 + lab] = s;
}

// ---------------- launch ----------------
extern "C" void kernel_launch(void* const* d_in, const int* in_sizes, int n_in,
                              void* d_out, int out_size) {
    const float* emb  = (const float*)d_in[0];
    const float* Win  = (const float*)d_in[1];
    const float* bin  = (const float*)d_in[2];
    const float* Wihf = (const float*)d_in[3];
    const float* Whhf = (const float*)d_in[4];
    const float* blf  = (const float*)d_in[5];
    const float* Wihb = (const float*)d_in[6];
    const float* Whhb = (const float*)d_in[7];
    const float* blb  = (const float*)d_in[8];
    const float* Wfc  = (const float*)d_in[9];
    const float* bfc  = (const float*)d_in[10];
    const float* Wout = (const float*)d_in[11];
    const float* bout = (const float*)d_in[12];
    const int*   x    = (const int*)d_in[13];
    const int*   mask = (const int*)d_in[14];
    const int*   len  = (const int*)d_in[15];
    float* out = (float*)d_out;

    k1a_gather<<<2048, 256>>>(emb, x);
    k1w_conv<<<256, KP_>>>(Win);
    k2w_conv<<<2048, 256>>>(Wihf, Wihb);
    k1b_hmma<<<dim3(128, 4), 256>>>(bin);
    k2_hmma<<<dim3(128, 16), 256>>>(blf, blb);
    k3_lstm<<<128, 256>>>(Whhf, Whhb, mask);
    k4a_fc<<<256, 256>>>(Wfc, bfc, len);
    k4b_out<<<1, 64>>>(Wout, bout, out);
}